// round 3
// baseline (speedup 1.0000x reference)
#include <cuda_runtime.h>
#include <cstdint>

#define NC 100
#define WPB 8
#define NBLOCKS 1184
#define MAX_PARTIALS 2048

__device__ float g_partials[MAX_PARTIALS];
__device__ unsigned int g_count = 0;

__device__ __forceinline__ uint32_t min16x2(uint32_t a, uint32_t b) {
    uint32_t d; asm("min.u16x2 %0,%1,%2;" : "=r"(d) : "r"(a), "r"(b)); return d;
}
__device__ __forceinline__ uint32_t max16x2(uint32_t a, uint32_t b) {
    uint32_t d; asm("max.u16x2 %0,%1,%2;" : "=r"(d) : "r"(a), "r"(b)); return d;
}

__global__ __launch_bounds__(256)
void pskd_main(const float* __restrict__ outp, const float* __restrict__ tgtp,
               int nrows, float inv_b, float* __restrict__ dout) {
    __shared__ float2 sh_to[WPB][4][128];
    __shared__ uint32_t sh_idx[WPB][4][32];
    __shared__ float sh_red[WPB];
    __shared__ int sh_last;

    const int warp = threadIdx.x >> 5;
    const int lane = threadIdx.x & 31;
    const int half = lane >> 4;       // 0: rows 0,1   1: rows 2,3
    const int hl = lane & 15;
    const int gwarp = blockIdx.x * WPB + warp;
    const int totw = gridDim.x * WPB;
    const int nquads = (nrows + 3) >> 2;

    float accP = 0.0f;   // all linear loss terms, reduced once at the end

    for (int q = gwarp; q < nquads; q += totw) {
        __syncwarp();

        const int rr0 = 4 * q + 2 * half;
        const int rr1 = rr0 + 1;
        const bool v0 = rr0 < nrows, v1 = rr1 < nrows;
        const size_t base0 = (size_t)(v0 ? rr0 : 0) * NC;
        const size_t base1 = (size_t)(v1 ? rr1 : 0) * NC;

        // lane hl owns slots 8hl..8hl+7 = float4 chunks 2hl, 2hl+1 (valid < 25)
        const int c0 = 2 * hl, c1 = 2 * hl + 1;
        float4 z = make_float4(0.f, 0.f, 0.f, 0.f);
        float4 t0a = z, t0b = z, o0a = z, o0b = z;
        float4 t1a = z, t1b = z, o1a = z, o1b = z;
        if (c0 < 25) {
            t0a = __ldg((const float4*)(tgtp + base0) + c0);
            o0a = __ldg((const float4*)(outp + base0) + c0);
            t1a = __ldg((const float4*)(tgtp + base1) + c0);
            o1a = __ldg((const float4*)(outp + base1) + c0);
        }
        if (c1 < 25) {
            t0b = __ldg((const float4*)(tgtp + base0) + c1);
            o0b = __ldg((const float4*)(outp + base0) + c1);
            t1b = __ldg((const float4*)(tgtp + base1) + c1);
            o1b = __ldg((const float4*)(outp + base1) + c1);
        }
        if (!v0) { t0a = t0b = o0a = o0b = z; }
        if (!v1) { t1a = t1b = o1a = o1b = z; }

        // sum(t*o) is sort-independent: fold into accP now (negative sign)
        {
            float s = 0.f;
            s = __fmaf_rn(t0a.x, o0a.x, s); s = __fmaf_rn(t0a.y, o0a.y, s);
            s = __fmaf_rn(t0a.z, o0a.z, s); s = __fmaf_rn(t0a.w, o0a.w, s);
            s = __fmaf_rn(t0b.x, o0b.x, s); s = __fmaf_rn(t0b.y, o0b.y, s);
            s = __fmaf_rn(t0b.z, o0b.z, s); s = __fmaf_rn(t0b.w, o0b.w, s);
            s = __fmaf_rn(t1a.x, o1a.x, s); s = __fmaf_rn(t1a.y, o1a.y, s);
            s = __fmaf_rn(t1a.z, o1a.z, s); s = __fmaf_rn(t1a.w, o1a.w, s);
            s = __fmaf_rn(t1b.x, o1b.x, s); s = __fmaf_rn(t1b.y, o1b.y, s);
            s = __fmaf_rn(t1b.z, o1b.z, s); s = __fmaf_rn(t1b.w, o1b.w, s);
            accP -= s;
        }

        // store (t,o) interleaved float2 per slot; float4 view index = slot/2
        {
            float4* p0 = reinterpret_cast<float4*>(&sh_to[warp][2 * half + 0][0]);
            float4* p1 = reinterpret_cast<float4*>(&sh_to[warp][2 * half + 1][0]);
            p0[4 * hl + 0] = make_float4(t0a.x, o0a.x, t0a.y, o0a.y);
            p0[4 * hl + 1] = make_float4(t0a.z, o0a.z, t0a.w, o0a.w);
            p0[4 * hl + 2] = make_float4(t0b.x, o0b.x, t0b.y, o0b.y);
            p0[4 * hl + 3] = make_float4(t0b.z, o0b.z, t0b.w, o0b.w);
            p1[4 * hl + 0] = make_float4(t1a.x, o1a.x, t1a.y, o1a.y);
            p1[4 * hl + 1] = make_float4(t1a.z, o1a.z, t1a.w, o1a.w);
            p1[4 * hl + 2] = make_float4(t1b.x, o1b.x, t1b.y, o1b.y);
            p1[4 * hl + 3] = make_float4(t1b.z, o1b.z, t1b.w, o1b.w);
        }

        // keys: low16 = first row, high16 = second row
        // key16 = (9 target bits) << 7 | (127 - slot)  -> descending bitonic
        uint32_t key[8];
        {
            float tv0[8] = {t0a.x, t0a.y, t0a.z, t0a.w, t0b.x, t0b.y, t0b.z, t0b.w};
            float tv1[8] = {t1a.x, t1a.y, t1a.z, t1a.w, t1b.x, t1b.y, t1b.z, t1b.w};
            #pragma unroll
            for (int e = 0; e < 8; e++) {
                uint32_t s = hl * 8 + e;
                uint32_t ka = ((__float_as_uint(tv0[e]) >> 15) & 0xFF80u) | (127u - s);
                uint32_t kb = ((__float_as_uint(tv1[e]) >> 15) & 0xFF80u) | (127u - s);
                key[e] = ka | (kb << 16);
            }
        }

        // bitonic sort, descending, 128 slots as 16 lanes x 8 elems,
        // two independent half-warp sorts (4 rows total, u16x2-packed)
        #pragma unroll
        for (int kk = 2; kk <= 128; kk <<= 1) {
            #pragma unroll
            for (int j = kk >> 1; j > 0; j >>= 1) {
                if (j >= 8) {
                    const int lj = j >> 3;
                    #pragma unroll
                    for (int e = 0; e < 8; e++) {
                        int g = hl * 8 + e;
                        uint32_t other = __shfl_xor_sync(0xffffffffu, key[e], lj);
                        bool take_max = (((g & kk) == 0) == ((g & j) == 0));
                        uint32_t mx = max16x2(key[e], other);
                        uint32_t mn = min16x2(key[e], other);
                        key[e] = take_max ? mx : mn;
                    }
                } else {
                    #pragma unroll
                    for (int e = 0; e < 8; e++) {
                        int p = e ^ j;
                        if (p > e) {
                            int g = hl * 8 + e;
                            bool up = ((g & kk) == 0);
                            uint32_t mx = max16x2(key[e], key[p]);
                            uint32_t mn = min16x2(key[e], key[p]);
                            key[e] = up ? mx : mn;
                            key[p] = up ? mn : mx;
                        }
                    }
                }
            }
        }

        // publish sorted original indices (byte-packed, 2 u32 per lane per row)
        {
            uint32_t ia0 = 0, ia1 = 0, ib0 = 0, ib1 = 0;
            #pragma unroll
            for (int e = 0; e < 4; e++) {
                ia0 |= (127u - (key[e] & 0x7Fu)) << (8 * e);
                ib0 |= (127u - ((key[e] >> 16) & 0x7Fu)) << (8 * e);
                ia1 |= (127u - (key[e + 4] & 0x7Fu)) << (8 * e);
                ib1 |= (127u - ((key[e + 4] >> 16) & 0x7Fu)) << (8 * e);
            }
            sh_idx[warp][2 * half + 0][2 * hl]     = ia0;
            sh_idx[warp][2 * half + 0][2 * hl + 1] = ia1;
            sh_idx[warp][2 * half + 1][2 * hl]     = ib0;
            sh_idx[warp][2 * half + 1][2 * hl + 1] = ib1;
        }
        __syncwarp();

        // per row: 20 rank-quintiles -> 19 windows; linear terms into accP,
        // only log(sum exp(o)) needs an immediate per-row reduction
        #pragma unroll
        for (int r = 0; r < 4; r++) {
            const bool vr = (4 * q + r) < nrows;
            const uint32_t* w32 = sh_idx[warp][r];
            const float2* to2 = sh_to[warp][r];

            float ga = 0.f, gb = 0.f, gc = 0.f;
            if (lane < 20) {
                int base = 5 * lane;
                uint64_t pk = ((uint64_t)w32[(base >> 2) + 1] << 32) | w32[base >> 2];
                pk >>= (base & 3) * 8;
                #pragma unroll
                for (int i = 0; i < 5; i++) {
                    int id = (int)((pk >> (8 * i)) & 0xFFu);
                    float2 to = to2[id];
                    float t = to.x, o = to.y;
                    float et = 1.0f + t * (1.0f + t * (0.5f + t * 0.16666667f));
                    ga += et;
                    gb = __fmaf_rn(et, o, gb);
                    gc += __expf(o);
                }
            }
            float A1 = __shfl_down_sync(0xffffffffu, ga, 1);
            float B1 = __shfl_down_sync(0xffffffffu, gb, 1);
            float C1 = __shfl_down_sync(0xffffffffu, gc, 1);
            float wl = 0.f;
            if (lane < 19)
                wl = __logf(gc + C1) - (gb + B1) / (ga + A1);

            float se = gc;
            #pragma unroll
            for (int off = 16; off > 0; off >>= 1)
                se += __shfl_down_sync(0xffffffffu, se, off);

            if (vr) {
                accP += 0.5f * wl;                 // lanes >= 19 have wl = 0
                if (lane == 0) accP += __logf(se); // sum_t == 1 to 1e-7
            }
        }
    }

    // single deferred reduction of all linear partials
    #pragma unroll
    for (int off = 16; off > 0; off >>= 1)
        accP += __shfl_down_sync(0xffffffffu, accP, off);
    if (lane == 0) sh_red[warp] = accP;
    __syncthreads();

    if (threadIdx.x == 0) {
        float s = 0.f;
        #pragma unroll
        for (int w = 0; w < WPB; w++) s += sh_red[w];
        g_partials[blockIdx.x] = s;
        __threadfence();
        unsigned int v = atomicAdd(&g_count, 1u);
        sh_last = (v == gridDim.x - 1) ? 1 : 0;
    }
    __syncthreads();

    if (sh_last) {
        float s = 0.f;
        for (int i = threadIdx.x; i < (int)gridDim.x; i += blockDim.x)
            s += g_partials[i];
        #pragma unroll
        for (int off = 16; off > 0; off >>= 1)
            s += __shfl_down_sync(0xffffffffu, s, off);
        if (lane == 0) sh_red[warp] = s;
        __syncthreads();
        if (threadIdx.x < 32) {
            float v2 = (threadIdx.x < WPB) ? sh_red[threadIdx.x] : 0.f;
            #pragma unroll
            for (int off = 16; off > 0; off >>= 1)
                v2 += __shfl_down_sync(0xffffffffu, v2, off);
            if (threadIdx.x == 0) {
                dout[0] = v2 * inv_b;
                g_count = 0;   // reset for next graph replay
            }
        }
    }
}

extern "C" void kernel_launch(void* const* d_in, const int* in_sizes, int n_in,
                              void* d_out, int out_size) {
    const float* outp = (const float*)d_in[0];   // 'output'
    const float* tgtp = (const float*)d_in[1];   // 'targets'
    int nrows = in_sizes[0] / NC;
    int nquads = (nrows + 3) >> 2;
    int blocks = NBLOCKS;
    int maxb = (nquads + WPB - 1) / WPB;
    if (blocks > maxb) blocks = maxb;
    if (blocks > MAX_PARTIALS) blocks = MAX_PARTIALS;
    pskd_main<<<blocks, WPB * 32>>>(outp, tgtp, nrows, 1.0f / (float)nrows,
                                    (float*)d_out);
}